// round 6
// baseline (speedup 1.0000x reference)
#include <cuda_runtime.h>

#define N_BINS 15
#define GRID   1184
#define TPB    256

// Per-block partial sums (no atomics across blocks, nothing to zero:
// every block fully writes its slot every run).
__device__ float g_part_conf[GRID][16];
__device__ float g_part_corr[GRID][16];

// Monotonic float->u32 transform: order(a) < order(b) <=> a < b.
__device__ __forceinline__ unsigned order_f32(float f) {
    unsigned u = __float_as_uint(f);
    return (u & 0x80000000u) ? ~u : (u | 0x80000000u);
}

// Half-warp per row: lanes 0-15 handle row 2p, lanes 16-31 row 2p+1.
// Each lane holds up to 8 logits (2 float4 chunks). Segmented redux.
__global__ void __launch_bounds__(TPB) ece_main_kernel(
    const float* __restrict__ logits,
    const int* __restrict__ labels,   // JAX x64-off: int64 demoted to int32
    int N)
{
    __shared__ float sConf[N_BINS];
    __shared__ float sCorr[N_BINS];

    const int tid  = threadIdx.x;
    const int lane = tid & 31;
    const int warp = tid >> 5;
    const int hl   = lane & 15;        // lane within half-warp
    const int half = lane >> 4;        // 0 or 1
    const unsigned mask = half ? 0xFFFF0000u : 0x0000FFFFu;
    const bool second = (hl < 9);      // chunk 16+hl exists (chunks 16..24)

    if (tid < N_BINS) { sConf[tid] = 0.0f; sCorr[tid] = 0.0f; }
    __syncthreads();

    const int gpair      = blockIdx.x * (TPB / 32) + warp;
    const int npairs     = gridDim.x * (TPB / 32);
    const int totalPairs = N >> 1;     // N is even (1e6)
    const float NEG_INF  = __int_as_float(0xff800000);
    const float4 NEG4    = make_float4(NEG_INF, NEG_INF, NEG_INF, NEG_INF);

    // Prefetch first pair.
    float4 a = NEG4, b = NEG4;
    int lab = 0;
    int pr = gpair;
    if (pr < totalPairs) {
        int r = 2 * pr + half;
        const float4* rp = (const float4*)(logits + (size_t)r * 100);
        a = __ldg(rp + hl);
        if (second) b = __ldg(rp + 16 + hl);
        lab = __ldg(labels + r);
    }

    for (; pr < totalPairs; pr += npairs) {
        float4 ca = a, cb = b;
        int clab = lab;

        // Prefetch next pair (overlaps with compute).
        int nxt = pr + npairs;
        if (nxt < totalPairs) {
            int r = 2 * nxt + half;
            const float4* rp = (const float4*)(logits + (size_t)r * 100);
            a = __ldg(rp + hl);
            if (second) b = __ldg(rp + 16 + hl);
            lab = __ldg(labels + r);
        }

        unsigned u0 = order_f32(ca.x), u1 = order_f32(ca.y);
        unsigned u2 = order_f32(ca.z), u3 = order_f32(ca.w);
        unsigned u4 = order_f32(cb.x), u5 = order_f32(cb.y);
        unsigned u6 = order_f32(cb.z), u7 = order_f32(cb.w);

        unsigned uloc = max(max(max(u0, u1), max(u2, u3)),
                            max(max(u4, u5), max(u6, u7)));
        unsigned km = __reduce_max_sync(mask, uloc);

        // Exact max value back from orderable bits.
        float m = (km & 0x80000000u) ? __uint_as_float(km & 0x7fffffffu)
                                     : __uint_as_float(~km);

        // argmax == label <=> orderbits at label position == km
        // (exact fp32 ties are measure-zero for random normal logits).
        int c  = clab >> 2;            // float4 chunk 0..24
        int ci = clab & 3;
        bool flag = false;
        if ((c & 15) == hl) {
            unsigned ul;
            if (c < 16) ul = (ci == 0) ? u0 : (ci == 1) ? u1 : (ci == 2) ? u2 : u3;
            else        ul = (ci == 0) ? u4 : (ci == 1) ? u5 : (ci == 2) ? u6 : u7;
            flag = (ul == km);
        }
        bool correct = __any_sync(mask, flag);

        // Sum of exp(x - m); exp(-inf) = 0 covers masked chunk lanes.
        float s = __expf(ca.x - m) + __expf(ca.y - m)
                + __expf(ca.z - m) + __expf(ca.w - m)
                + __expf(cb.x - m) + __expf(cb.y - m)
                + __expf(cb.z - m) + __expf(cb.w - m);

        // Fixed-point 2^-24 sum: S <= 100*2^24 < 2^32.
        unsigned si = __float2uint_rn(s * 16777216.0f);
        unsigned S  = __reduce_add_sync(mask, si);

        if (hl == 0) {
            float conf = 16777216.0f / (float)S;   // softmax at argmax
            // bin i holds conf in (i/15, (i+1)/15] -> ceil(conf*15)-1
            int bn = (int)ceilf(conf * (float)N_BINS) - 1;
            bn = bn < 0 ? 0 : (bn > N_BINS - 1 ? N_BINS - 1 : bn);
            atomicAdd(&sConf[bn], conf);
            if (correct)
                atomicAdd(&sCorr[bn], 1.0f);       // ~1% of rows
        }
    }

    __syncthreads();
    if (tid < N_BINS) {
        g_part_conf[blockIdx.x][tid] = sConf[tid];
        g_part_corr[blockIdx.x][tid] = sCorr[tid];
    }
}

// Reduce per-block partials: ece = sum_b |sum_conf_b - sum_corr_b| / N.
__global__ void __launch_bounds__(TPB) ece_final_kernel(
    float* __restrict__ out, float invN, int nblocks)
{
    __shared__ float acc[N_BINS][17];
    __shared__ float binAbs[N_BINS];

    int t = threadIdx.x;
    int bin = t >> 4;   // 0..15
    int i   = t & 15;

    float d = 0.0f;
    if (bin < N_BINS) {
        for (int blk = i; blk < nblocks; blk += 16)
            d += g_part_conf[blk][bin] - g_part_corr[blk][bin];
        acc[bin][i] = d;
    }
    __syncthreads();

    if (t < N_BINS) {
        float v = 0.0f;
        #pragma unroll
        for (int j = 0; j < 16; j++) v += acc[t][j];
        binAbs[t] = fabsf(v);
    }
    __syncthreads();

    if (t == 0) {
        float s = 0.0f;
        #pragma unroll
        for (int bn = 0; bn < N_BINS; bn++) s += binAbs[bn];
        out[0] = s * invN;
    }
}

extern "C" void kernel_launch(void* const* d_in, const int* in_sizes, int n_in,
                              void* d_out, int out_size)
{
    const float* logits = (const float*)d_in[0];
    const int*   labels = (const int*)d_in[1];
    const int N = in_sizes[1];          // label count = number of rows

    ece_main_kernel<<<GRID, TPB>>>(logits, labels, N);
    ece_final_kernel<<<1, TPB>>>((float*)d_out, 1.0f / (float)N, GRID);
}

// round 7
// speedup vs baseline: 1.4007x; 1.4007x over previous
#include <cuda_runtime.h>

#define N_BINS 15
#define GRID   1184
#define TPB    256
#define WARPS  (TPB / 32)

// Per-block partial sums (no atomics anywhere; every block fully
// rewrites its slot every run, so nothing needs zeroing).
__device__ float g_part_conf[GRID][16];
__device__ float g_part_corr[GRID][16];

// Monotonic float->u32 transform: order(a) < order(b) <=> a < b.
__device__ __forceinline__ unsigned order_f32(float f) {
    unsigned u = __float_as_uint(f);
    return (u & 0x80000000u) ? ~u : (u | 0x80000000u);
}

// One warp per row of 100 fp32 logits (25 float4 lanes). Single pass.
// No atomics: lane i keeps the register accumulator for bin i; the
// redux results are warp-uniform so every lane derives conf/bin/correct.
__global__ void __launch_bounds__(TPB) ece_main_kernel(
    const float* __restrict__ logits,
    const int* __restrict__ labels,   // JAX x64-off: int64 demoted to int32
    int N)
{
    __shared__ float sConf[WARPS][16];
    __shared__ float sCorr[WARPS][16];

    const int tid  = threadIdx.x;
    const int lane = tid & 31;
    const int warp = tid >> 5;
    const bool active = (lane < 25);
    const float NEG_INF = __int_as_float(0xff800000);

    const int gwarp  = blockIdx.x * WARPS + warp;
    const int nwarps = gridDim.x * WARPS;

    // Register bin accumulators (lane i < 15 owns bin i).
    float accConf = 0.0f;
    float accCorr = 0.0f;

    // Prefetch first row.
    float4 f4 = make_float4(NEG_INF, NEG_INF, NEG_INF, NEG_INF);
    int lab = -1;
    int row = gwarp;
    if (row < N) {
        if (active)
            f4 = __ldg((const float4*)(logits + (size_t)row * 100) + lane);
        lab = __ldg(labels + row);
    }

    for (; row < N; row += nwarps) {
        float4 cur = f4;
        int curlab = lab;

        // Prefetch next row (overlaps the compute below).
        int nxt = row + nwarps;
        if (nxt < N) {
            if (active)
                f4 = __ldg((const float4*)(logits + (size_t)nxt * 100) + lane);
            lab = __ldg(labels + nxt);
        }

        unsigned u0 = active ? order_f32(cur.x) : 0u;
        unsigned u1 = active ? order_f32(cur.y) : 0u;
        unsigned u2 = active ? order_f32(cur.z) : 0u;
        unsigned u3 = active ? order_f32(cur.w) : 0u;

        unsigned uloc = max(max(u0, u1), max(u2, u3));
        unsigned km = __reduce_max_sync(0xffffffffu, uloc);

        // Exact max value back from orderable bits.
        float m = (km & 0x80000000u) ? __uint_as_float(km & 0x7fffffffu)
                                     : __uint_as_float(~km);

        // argmax == label <=> orderbits at the label position == km
        // (exact fp32 ties are measure-zero for random normal logits).
        bool flag = false;
        if (lane == (curlab >> 2)) {
            unsigned ul = (curlab & 3) == 0 ? u0 :
                          (curlab & 3) == 1 ? u1 :
                          (curlab & 3) == 2 ? u2 : u3;
            flag = (ul == km);
        }
        bool correct = __any_sync(0xffffffffu, flag);   // warp-uniform

        // Sum of exp(x - m) in 2^-24 fixed point (S <= 100 -> fits u32).
        float s = 0.0f;
        if (active) {
            s = __expf(cur.x - m) + __expf(cur.y - m)
              + __expf(cur.z - m) + __expf(cur.w - m);
        }
        unsigned si = __float2uint_rn(s * 16777216.0f);
        unsigned Ssum = __reduce_add_sync(0xffffffffu, si);  // warp-uniform

        // Every lane computes conf/bin redundantly (ALU is free);
        // only the lane owning that bin accumulates. Zero atomics.
        float conf = 16777216.0f / (float)Ssum;   // softmax at argmax
        // bin i holds conf in (i/15, (i+1)/15] -> ceil(conf*15)-1
        int b = (int)ceilf(conf * (float)N_BINS) - 1;
        b = b < 0 ? 0 : (b > N_BINS - 1 ? N_BINS - 1 : b);
        if (lane == b) {
            accConf += conf;
            if (correct) accCorr += 1.0f;
        }
    }

    // Per-warp accumulators -> smem (single store per lane).
    if (lane < N_BINS) {
        sConf[warp][lane] = accConf;
        sCorr[warp][lane] = accCorr;
    }
    __syncthreads();

    // Block reduce: thread bin<15 sums across the 8 warps.
    if (tid < N_BINS) {
        float c = 0.0f, k = 0.0f;
        #pragma unroll
        for (int w = 0; w < WARPS; w++) {
            c += sConf[w][tid];
            k += sCorr[w][tid];
        }
        g_part_conf[blockIdx.x][tid] = c;
        g_part_corr[blockIdx.x][tid] = k;
    }
}

// Reduce per-block partials: ece = sum_b |sum_conf_b - sum_corr_b| / N.
__global__ void __launch_bounds__(TPB) ece_final_kernel(
    float* __restrict__ out, float invN, int nblocks)
{
    __shared__ float acc[N_BINS][17];
    __shared__ float binAbs[N_BINS];

    int t = threadIdx.x;
    int bin = t >> 4;   // 0..15
    int i   = t & 15;

    if (bin < N_BINS) {
        float d = 0.0f;
        for (int blk = i; blk < nblocks; blk += 16)
            d += g_part_conf[blk][bin] - g_part_corr[blk][bin];
        acc[bin][i] = d;
    }
    __syncthreads();

    if (t < N_BINS) {
        float v = 0.0f;
        #pragma unroll
        for (int j = 0; j < 16; j++) v += acc[t][j];
        binAbs[t] = fabsf(v);
    }
    __syncthreads();

    if (t == 0) {
        float s = 0.0f;
        #pragma unroll
        for (int bn = 0; bn < N_BINS; bn++) s += binAbs[bn];
        out[0] = s * invN;
    }
}

extern "C" void kernel_launch(void* const* d_in, const int* in_sizes, int n_in,
                              void* d_out, int out_size)
{
    const float* logits = (const float*)d_in[0];
    const int*   labels = (const int*)d_in[1];
    const int N = in_sizes[1];          // label count = number of rows

    ece_main_kernel<<<GRID, TPB>>>(logits, labels, N);
    ece_final_kernel<<<1, TPB>>>((float*)d_out, 1.0f / (float)N, GRID);
}